// round 12
// baseline (speedup 1.0000x reference)
#include <cuda_runtime.h>

#define NN 500000   // N_NODES upper bound
#define TB 256
#define EPT 4       // edges per thread in edge kernels

// Scratch (no cudaMalloc allowed). 16B-aligned for float4 vector access.
__device__ int    g_is64;
__device__ int    g_b1zero;
__device__ __align__(16) float  g_deg [NN];
__device__ __align__(16) float  g_dinv[NN];
__device__ __align__(16) float  g_v   [NN];   // dinv*x   (gather, layer 1)
__device__ __align__(16) float  g_s   [NN];   // layer-1 accumulator (init = self-loop)
__device__ __align__(16) float  g_val [NN];   // dinv*pre (gather, layer 2 fast path)
__device__ __align__(16) float2 g_sb  [NN];   // (Σ max(val,0), Σ max(-val,0)) at dst
__device__ __align__(16) float4 g_h2d [NN];   // fallback payload (b1 != 0)

// ---------------- PDL primitives ----------------
__device__ __forceinline__ void pdl_wait() {
    asm volatile("griddepcontrol.wait;" ::: "memory");
}
__device__ __forceinline__ void pdl_launch_dependents() {
    asm volatile("griddepcontrol.launch_dependents;");
}

// ---------------- cache-controlled loads (edge kernels) ----------------
__device__ __forceinline__ int ld_idx32_na(const int* p) {
    int v;
    asm volatile("ld.global.L1::no_allocate.b32 %0, [%1];" : "=r"(v) : "l"(p));
    return v;
}
__device__ __forceinline__ int ld_idx64_na(const long long* p) {
    long long v;
    asm volatile("ld.global.L1::no_allocate.b64 %0, [%1];" : "=l"(v) : "l"(p));
    return (int)v;
}
__device__ __forceinline__ int4 ld_idx32x4_na(const int4* p) {
    int4 v;
    asm volatile("ld.global.L1::no_allocate.v4.b32 {%0,%1,%2,%3}, [%4];"
                 : "=r"(v.x), "=r"(v.y), "=r"(v.z), "=r"(v.w) : "l"(p));
    return v;
}
__device__ __forceinline__ float ld_gather_el(const float* p) {
    float v;
    asm volatile("ld.global.nc.L1::evict_last.f32 %0, [%1];" : "=f"(v) : "l"(p));
    return v;
}
__device__ __forceinline__ int load_idx(const void* ei, long long e, int is64) {
    if (is64) return ld_idx64_na(((const long long*)ei) + e);
    return ld_idx32_na(((const int*)ei) + e);
}

// ---------------- probe + degree init (fused, vectorized) ----------------
__global__ void k_probe_init(const void* ei, int E, int n, const float* __restrict__ b1) {
    int t = blockIdx.x * blockDim.x + threadIdx.x;
    int base = t * 4;
    if (base + 3 < n) {
        *reinterpret_cast<float4*>(&g_deg[base]) = make_float4(1.f, 1.f, 1.f, 1.f);
    } else {
        for (int j = base; j < n; j++) g_deg[j] = 1.0f;
    }
    if (blockIdx.x == 0) {
        __shared__ int ok;
        if (threadIdx.x == 0) ok = 1;
        __syncthreads();
        const long long* p = (const long long*)ei;
        long long stride = E / blockDim.x;
        if (stride < 1) stride = 1;
        long long idx = (long long)threadIdx.x * stride;
        if (idx < E) {
            long long v = p[idx];
            if (v < 0 || v >= (long long)n) ok = 0;
        }
        __syncthreads();
        if (threadIdx.x == 0) {
            g_is64 = ok;
            g_b1zero = (b1[0] == 0.0f && b1[1] == 0.0f &&
                        b1[2] == 0.0f && b1[3] == 0.0f) ? 1 : 0;
        }
    }
    pdl_launch_dependents();
}

// ---------------- node kernels: 4 nodes/thread, float4 I/O ----------------

__global__ void k_dinv(const float* __restrict__ x, int n) {
    pdl_wait();                                   // needs g_deg complete
    int t = blockIdx.x * blockDim.x + threadIdx.x;
    int base = t * 4;
    if (base + 3 < n) {
        float4 dg = *reinterpret_cast<const float4*>(&g_deg[base]);
        float4 xx = *reinterpret_cast<const float4*>(&x[base]);
        float4 di = make_float4(rsqrtf(dg.x), rsqrtf(dg.y), rsqrtf(dg.z), rsqrtf(dg.w));
        float4 v  = make_float4(di.x*xx.x, di.y*xx.y, di.z*xx.z, di.w*xx.w);
        *reinterpret_cast<float4*>(&g_dinv[base]) = di;
        *reinterpret_cast<float4*>(&g_v[base])    = v;
        *reinterpret_cast<float4*>(&g_s[base])    = v;   // self-loop, layer 1
    } else {
        for (int j = base; j < n; j++) {
            float di = rsqrtf(g_deg[j]);
            g_dinv[j] = di;
            float v = di * x[j];
            g_v[j] = v;
            g_s[j] = v;
        }
    }
    pdl_launch_dependents();
}

__device__ __forceinline__ void mid_one(int i, float di, float s,
                                        const float* W1, const float* b1,
                                        const float* W2, float4* out, int b1z) {
    float pre = di * s;
    float val = di * pre;
    g_val[i] = val;
    g_sb [i] = make_float2(fmaxf(val, 0.0f), fmaxf(-val, 0.0f));
    if (!b1z) {
        float h[4];
#pragma unroll
        for (int c = 0; c < 4; c++)
            h[c] = fmaxf(fmaf(pre, __ldg(&W1[c]), __ldg(&b1[c])), 0.0f);
        float4 v;
        v.x = di * (h[0]*__ldg(&W2[0]) + h[1]*__ldg(&W2[4]) + h[2]*__ldg(&W2[8])  + h[3]*__ldg(&W2[12]));
        v.y = di * (h[0]*__ldg(&W2[1]) + h[1]*__ldg(&W2[5]) + h[2]*__ldg(&W2[9])  + h[3]*__ldg(&W2[13]));
        v.z = di * (h[0]*__ldg(&W2[2]) + h[1]*__ldg(&W2[6]) + h[2]*__ldg(&W2[10]) + h[3]*__ldg(&W2[14]));
        v.w = di * (h[0]*__ldg(&W2[3]) + h[1]*__ldg(&W2[7]) + h[2]*__ldg(&W2[11]) + h[3]*__ldg(&W2[15]));
        g_h2d[i] = v;
        out[i]   = v;
    }
}

__global__ void k_mid(const float* __restrict__ W1, const float* __restrict__ b1,
                      const float* __restrict__ W2,
                      float4* __restrict__ out, int n) {
    pdl_wait();                                   // needs g_s complete
    int t = blockIdx.x * blockDim.x + threadIdx.x;
    int base = t * 4;
    int b1z = g_b1zero;
    if (base + 3 < n) {
        float4 di = *reinterpret_cast<const float4*>(&g_dinv[base]);
        float4 ss = *reinterpret_cast<const float4*>(&g_s[base]);
        if (b1z) {
            float4 pre = make_float4(di.x*ss.x, di.y*ss.y, di.z*ss.z, di.w*ss.w);
            float4 val = make_float4(di.x*pre.x, di.y*pre.y, di.z*pre.z, di.w*pre.w);
            *reinterpret_cast<float4*>(&g_val[base]) = val;
            float4 sb01 = make_float4(fmaxf(val.x,0.f), fmaxf(-val.x,0.f),
                                      fmaxf(val.y,0.f), fmaxf(-val.y,0.f));
            float4 sb23 = make_float4(fmaxf(val.z,0.f), fmaxf(-val.z,0.f),
                                      fmaxf(val.w,0.f), fmaxf(-val.w,0.f));
            float4* sbp = reinterpret_cast<float4*>(&g_sb[base]);
            sbp[0] = sb01;
            sbp[1] = sb23;
        } else {
            mid_one(base+0, di.x, ss.x, W1, b1, W2, out, b1z);
            mid_one(base+1, di.y, ss.y, W1, b1, W2, out, b1z);
            mid_one(base+2, di.z, ss.z, W1, b1, W2, out, b1z);
            mid_one(base+3, di.w, ss.w, W1, b1, W2, out, b1z);
        }
    } else {
        for (int j = base; j < n; j++) mid_one(j, g_dinv[j], g_s[j], W1, b1, W2, out, b1z);
    }
    pdl_launch_dependents();
}

__global__ void k_final(const float* __restrict__ W1, const float* __restrict__ W2,
                        const float* __restrict__ b2,
                        float4* __restrict__ out, int n) {
    pdl_wait();                                   // needs g_sb complete
    int t = blockIdx.x * blockDim.x + threadIdx.x;
    int base = t * 4;
    if (g_b1zero) {
        float up[4], un[4];
#pragma unroll
        for (int c = 0; c < 4; c++) {
            float a = 0.f, b = 0.f;
#pragma unroll
            for (int k = 0; k < 4; k++) {
                float w = __ldg(&W1[k]);
                float w2 = __ldg(&W2[k*4 + c]);
                a = fmaf(fmaxf(w, 0.f),  w2, a);
                b = fmaf(fmaxf(-w, 0.f), w2, b);
            }
            up[c] = a; un[c] = b;
        }
        if (base + 3 < n) {
            float4 di = *reinterpret_cast<const float4*>(&g_dinv[base]);
            const float4* sbp = reinterpret_cast<const float4*>(&g_sb[base]);
            float4 sb01 = sbp[0], sb23 = sbp[1];
            float dia[4] = {di.x, di.y, di.z, di.w};
            float spa[4] = {sb01.x, sb01.z, sb23.x, sb23.z};
            float sna[4] = {sb01.y, sb01.w, sb23.y, sb23.w};
#pragma unroll
            for (int j = 0; j < 4; j++) {
                float4 o;
                o.x = fmaf(dia[j], spa[j]*up[0] + sna[j]*un[0], __ldg(&b2[0]));
                o.y = fmaf(dia[j], spa[j]*up[1] + sna[j]*un[1], __ldg(&b2[1]));
                o.z = fmaf(dia[j], spa[j]*up[2] + sna[j]*un[2], __ldg(&b2[2]));
                o.w = fmaf(dia[j], spa[j]*up[3] + sna[j]*un[3], __ldg(&b2[3]));
                out[base + j] = o;
            }
        } else {
            for (int j = base; j < n; j++) {
                float di = g_dinv[j];
                float2 sb = g_sb[j];
                float4 o;
                o.x = fmaf(di, sb.x*up[0] + sb.y*un[0], __ldg(&b2[0]));
                o.y = fmaf(di, sb.x*up[1] + sb.y*un[1], __ldg(&b2[1]));
                o.z = fmaf(di, sb.x*up[2] + sb.y*un[2], __ldg(&b2[2]));
                o.w = fmaf(di, sb.x*up[3] + sb.y*un[3], __ldg(&b2[3]));
                out[j] = o;
            }
        }
    } else {
        for (int j = base; j < min(base + 4, n); j++) {
            float di = g_dinv[j];
            float4 o = out[j];
            out[j] = make_float4(fmaf(di, o.x, __ldg(&b2[0])),
                                 fmaf(di, o.y, __ldg(&b2[1])),
                                 fmaf(di, o.z, __ldg(&b2[2])),
                                 fmaf(di, o.w, __ldg(&b2[3])));
        }
    }
}

// ---------------- edge kernels ----------------

__global__ void __launch_bounds__(TB) k_deg(const void* __restrict__ ei, int E, int n) {
    pdl_wait();                                   // needs g_deg init + g_is64
    int vec = (!g_is64) && ((E & 3) == 0);
    if (vec) {
        int t = blockIdx.x * blockDim.x + threadIdx.x;
        if (t * 4 < E) {
            const int4* dst4 = (const int4*)ei + (E >> 2);
            int4 d4 = ld_idx32x4_na(&dst4[t]);
            if ((unsigned)d4.x < (unsigned)n) atomicAdd(&g_deg[d4.x], 1.0f);
            if ((unsigned)d4.y < (unsigned)n) atomicAdd(&g_deg[d4.y], 1.0f);
            if ((unsigned)d4.z < (unsigned)n) atomicAdd(&g_deg[d4.z], 1.0f);
            if ((unsigned)d4.w < (unsigned)n) atomicAdd(&g_deg[d4.w], 1.0f);
        }
    } else {
        int is64 = g_is64;
        int e0 = blockIdx.x * blockDim.x * EPT + threadIdx.x;
        for (int k = 0; k < EPT; k++) {
            int e = e0 + k * blockDim.x;
            if (e < E) {
                int d = load_idx(ei, (long long)e + E, is64);
                if ((unsigned)d < (unsigned)n) atomicAdd(&g_deg[d], 1.0f);
            }
        }
    }
    pdl_launch_dependents();
}

// Scatter kernels: index loads are independent of the immediate predecessor
// (edge_index + g_is64 finalized 2+ kernels upstream, transitively complete
// under the PDL chain), so they're hoisted BEFORE pdl_wait to overlap the
// predecessor's tail.
__global__ void __launch_bounds__(TB) k_scatter1(const void* __restrict__ ei, int E, int n) {
    int is64 = g_is64;
    int e0 = blockIdx.x * blockDim.x * EPT + threadIdx.x;
    int s[EPT], d[EPT];
#pragma unroll
    for (int k = 0; k < EPT; k++) {
        int e = e0 + k * blockDim.x;
        if (e < E) {
            s[k] = load_idx(ei, e, is64);
            d[k] = load_idx(ei, (long long)e + E, is64);
        } else d[k] = -1;
    }
    pdl_wait();                                   // needs g_v / g_s from k_dinv
#pragma unroll
    for (int k = 0; k < EPT; k++) {
        if (d[k] >= 0 && (unsigned)s[k] < (unsigned)n && (unsigned)d[k] < (unsigned)n)
            atomicAdd(&g_s[d[k]], ld_gather_el(&g_v[s[k]]));
    }
    pdl_launch_dependents();
}

__global__ void __launch_bounds__(TB) k_scatter2(const void* __restrict__ ei,
                                                 float4* __restrict__ out, int E, int n) {
    int is64 = g_is64;
    int fast = g_b1zero;
    int e0 = blockIdx.x * blockDim.x * EPT + threadIdx.x;
    int s[EPT], d[EPT];
#pragma unroll
    for (int k = 0; k < EPT; k++) {
        int e = e0 + k * blockDim.x;
        if (e < E) {
            s[k] = load_idx(ei, e, is64);
            d[k] = load_idx(ei, (long long)e + E, is64);
        } else d[k] = -1;
    }
    pdl_wait();                                   // needs g_val / g_sb from k_mid
#pragma unroll
    for (int k = 0; k < EPT; k++) {
        if (d[k] >= 0 && (unsigned)s[k] < (unsigned)n && (unsigned)d[k] < (unsigned)n) {
            if (fast) {
                float v  = ld_gather_el(&g_val[s[k]]);
                float vp = fmaxf(v, 0.0f);
                float vn = fmaxf(-v, 0.0f);
                float* p = reinterpret_cast<float*>(&g_sb[d[k]]);
                asm volatile("red.global.add.v2.f32 [%0], {%1,%2};"
                             :: "l"(p), "f"(vp), "f"(vn)
                             : "memory");
            } else {
                float4 m = __ldg(&g_h2d[s[k]]);
                float* p = reinterpret_cast<float*>(&out[d[k]]);
                asm volatile("red.global.add.v4.f32 [%0], {%1,%2,%3,%4};"
                             :: "l"(p), "f"(m.x), "f"(m.y), "f"(m.z), "f"(m.w)
                             : "memory");
            }
        }
    }
    pdl_launch_dependents();
}

// ---------------- launch ----------------

template <typename F, typename... Args>
static void launch_pdl(F func, int grid, int block, Args... args) {
    cudaLaunchConfig_t cfg = {};
    cfg.gridDim  = dim3(grid, 1, 1);
    cfg.blockDim = dim3(block, 1, 1);
    cudaLaunchAttribute attr[1];
    attr[0].id = cudaLaunchAttributeProgrammaticStreamSerialization;
    attr[0].val.programmaticStreamSerializationAllowed = 1;
    cfg.attrs = attr;
    cfg.numAttrs = 1;
    cudaLaunchKernelEx(&cfg, func, args...);
}

extern "C" void kernel_launch(void* const* d_in, const int* in_sizes, int n_in,
                              void* d_out, int out_size) {
    const float* x  = (const float*)d_in[0];
    const void*  ei = d_in[1];
    const float* W1 = (const float*)d_in[2];
    const float* b1 = (const float*)d_in[3];
    const float* W2 = (const float*)d_in[4];
    const float* b2 = (const float*)d_in[5];
    float4* out = (float4*)d_out;

    int n = in_sizes[0];
    int E = in_sizes[1] / 2;

    int nb_node4 = (n + TB * 4 - 1) / (TB * 4);   // 4 nodes/thread
    int nb_edge  = (E + TB * EPT - 1) / (TB * EPT);

    k_probe_init <<<nb_node4, TB>>>(ei, E, n, b1);                 // 1 (plain)
    launch_pdl(k_deg,      nb_edge,  TB, ei, E, n);                // 2
    launch_pdl(k_dinv,     nb_node4, TB, x, n);                    // 3
    launch_pdl(k_scatter1, nb_edge,  TB, ei, E, n);                // 4
    launch_pdl(k_mid,      nb_node4, TB, W1, b1, W2, out, n);      // 5
    launch_pdl(k_scatter2, nb_edge,  TB, ei, out, E, n);           // 6
    launch_pdl(k_final,    nb_node4, TB, W1, W2, b2, out, n);      // 7
}

// round 13
// speedup vs baseline: 1.0249x; 1.0249x over previous
#include <cuda_runtime.h>

#define NN 500000   // N_NODES upper bound
#define TB 256
#define EPT 4       // edges per thread in edge kernels

// Scratch (no cudaMalloc allowed).
__device__ int    g_is64;        // 1 if edge_index is int64, 0 if int32
__device__ int    g_b1zero;      // 1 if b1 == 0 (enables scalar layer-2 path)
__device__ float  g_deg [NN];    // degree (float; exact for counts < 2^24)
__device__ float  g_dinv[NN];    // deg^{-1/2}
__device__ float  g_v   [NN];    // dinv[i] * x[i]          (gather source, layer 1)
__device__ float  g_s   [NN];    // layer-1 accumulator (init = self-loop term)
__device__ float  g_val [NN];    // dinv*pre                (gather, layer 2 fast path)
__device__ float2 g_sb  [NN];    // (Σ max(val,0), Σ max(-val,0)) at dst
__device__ float4 g_h2d [NN];    // fallback payload (b1 != 0)

// ---------------- PDL primitives ----------------
__device__ __forceinline__ void pdl_wait() {
    asm volatile("griddepcontrol.wait;" ::: "memory");
}
__device__ __forceinline__ void pdl_launch_dependents() {
    asm volatile("griddepcontrol.launch_dependents;");
}

// ---------------- edge-index loads (streaming) ----------------
__device__ __forceinline__ int load_idx_cs(const void* ei, long long e, int is64) {
    if (is64) return (int)__ldcs(((const long long*)ei) + e);
    return __ldcs(((const int*)ei) + e);
}

// ---------------- probe + degree init (fused) ----------------
__global__ void k_probe_init(const void* ei, int E, int n, const float* __restrict__ b1) {
    int i = blockIdx.x * blockDim.x + threadIdx.x;
    if (i < n) g_deg[i] = 1.0f;              // self-loop
    if (blockIdx.x == 0) {
        // dtype probe: as int64, genuine int64 indices are in [0,n).
        // int32 misread as int64 gives lo + hi*2^32, out of range unless hi==0.
        __shared__ int ok;
        if (threadIdx.x == 0) ok = 1;
        __syncthreads();
        const long long* p = (const long long*)ei;
        long long stride = E / blockDim.x;
        if (stride < 1) stride = 1;
        long long idx = (long long)threadIdx.x * stride;
        if (idx < E) {   // first E int64 slots in-bounds under BOTH interpretations
            long long v = p[idx];
            if (v < 0 || v >= (long long)n) ok = 0;
        }
        __syncthreads();
        if (threadIdx.x == 0) {
            g_is64 = ok;
            g_b1zero = (b1[0] == 0.0f && b1[1] == 0.0f &&
                        b1[2] == 0.0f && b1[3] == 0.0f) ? 1 : 0;
        }
    }
    pdl_launch_dependents();
}

// ---------------- node kernels ----------------

__global__ void k_dinv(const float* __restrict__ x, int n) {
    pdl_wait();
    int i = blockIdx.x * blockDim.x + threadIdx.x;
    if (i < n) {
        float di = rsqrtf(g_deg[i]);         // deg >= 1 always (self-loop)
        g_dinv[i] = di;
        float v = di * x[i];
        g_v[i] = v;
        g_s[i] = v;                          // self-loop contribution, layer 1
    }
    pdl_launch_dependents();
}

__global__ void k_mid(const float* __restrict__ W1, const float* __restrict__ b1,
                      const float* __restrict__ W2,
                      float4* __restrict__ out, int n) {
    pdl_wait();
    int i = blockIdx.x * blockDim.x + threadIdx.x;
    if (i < n) {
        float di  = g_dinv[i];
        float pre = di * g_s[i];
        float val = di * pre;
        g_val[i] = val;
        g_sb [i] = make_float2(fmaxf(val, 0.0f), fmaxf(-val, 0.0f));  // self-loop, layer 2
        if (!g_b1zero) {                     // fallback representation (b1 != 0)
            float h[4];
#pragma unroll
            for (int c = 0; c < 4; c++)
                h[c] = fmaxf(fmaf(pre, __ldg(&W1[c]), __ldg(&b1[c])), 0.0f);
            float4 v;
            v.x = di * (h[0]*__ldg(&W2[0]) + h[1]*__ldg(&W2[4]) + h[2]*__ldg(&W2[8])  + h[3]*__ldg(&W2[12]));
            v.y = di * (h[0]*__ldg(&W2[1]) + h[1]*__ldg(&W2[5]) + h[2]*__ldg(&W2[9])  + h[3]*__ldg(&W2[13]));
            v.z = di * (h[0]*__ldg(&W2[2]) + h[1]*__ldg(&W2[6]) + h[2]*__ldg(&W2[10]) + h[3]*__ldg(&W2[14]));
            v.w = di * (h[0]*__ldg(&W2[3]) + h[1]*__ldg(&W2[7]) + h[2]*__ldg(&W2[11]) + h[3]*__ldg(&W2[15]));
            g_h2d[i] = v;
            out[i]   = v;
        }
    }
    pdl_launch_dependents();
}

__global__ void k_final(const float* __restrict__ W1, const float* __restrict__ W2,
                        const float* __restrict__ b2,
                        float4* __restrict__ out, int n) {
    pdl_wait();
    int i = blockIdx.x * blockDim.x + threadIdx.x;
    if (i >= n) return;
    float di = g_dinv[i];
    if (g_b1zero) {
        float gp[4], gn[4];
#pragma unroll
        for (int k = 0; k < 4; k++) {
            float w = __ldg(&W1[k]);
            gp[k] = fmaxf(w, 0.0f);
            gn[k] = fmaxf(-w, 0.0f);
        }
        float2 sb = g_sb[i];
        float o[4];
#pragma unroll
        for (int c = 0; c < 4; c++) {
            float up = gp[0]*__ldg(&W2[0*4+c]) + gp[1]*__ldg(&W2[1*4+c])
                     + gp[2]*__ldg(&W2[2*4+c]) + gp[3]*__ldg(&W2[3*4+c]);
            float un = gn[0]*__ldg(&W2[0*4+c]) + gn[1]*__ldg(&W2[1*4+c])
                     + gn[2]*__ldg(&W2[2*4+c]) + gn[3]*__ldg(&W2[3*4+c]);
            o[c] = fmaf(di, sb.x*up + sb.y*un, __ldg(&b2[c]));
        }
        out[i] = make_float4(o[0], o[1], o[2], o[3]);
    } else {
        float4 o = out[i];
        out[i] = make_float4(fmaf(di, o.x, __ldg(&b2[0])),
                             fmaf(di, o.y, __ldg(&b2[1])),
                             fmaf(di, o.z, __ldg(&b2[2])),
                             fmaf(di, o.w, __ldg(&b2[3])));
    }
}

// ---------------- edge kernels (bodies identical to best-known config;
// pdl_wait FIRST, no load hoisting) ----------------

__global__ void __launch_bounds__(TB) k_deg(const void* __restrict__ ei, int E, int n) {
    pdl_wait();
    int is64 = g_is64;
    int e0 = blockIdx.x * blockDim.x * EPT + threadIdx.x;
    for (int k = 0; k < EPT; k++) {
        int e = e0 + k * blockDim.x;
        if (e < E) {
            int d = load_idx_cs(ei, (long long)e + E, is64);
            if ((unsigned)d < (unsigned)n) atomicAdd(&g_deg[d], 1.0f);
        }
    }
    pdl_launch_dependents();
}

__global__ void __launch_bounds__(TB) k_scatter1(const void* __restrict__ ei, int E, int n) {
    pdl_wait();
    int is64 = g_is64;
    int e0 = blockIdx.x * blockDim.x * EPT + threadIdx.x;
    for (int k = 0; k < EPT; k++) {
        int e = e0 + k * blockDim.x;
        if (e < E) {
            int s = load_idx_cs(ei, e, is64);
            int d = load_idx_cs(ei, (long long)e + E, is64);
            if ((unsigned)s < (unsigned)n && (unsigned)d < (unsigned)n)
                atomicAdd(&g_s[d], __ldg(&g_v[s]));
        }
    }
    pdl_launch_dependents();
}

__global__ void __launch_bounds__(TB) k_scatter2(const void* __restrict__ ei,
                                                 float4* __restrict__ out, int E, int n) {
    pdl_wait();
    int is64 = g_is64;
    int fast = g_b1zero;
    int e0 = blockIdx.x * blockDim.x * EPT + threadIdx.x;
    for (int k = 0; k < EPT; k++) {
        int e = e0 + k * blockDim.x;
        if (e < E) {
            int s = load_idx_cs(ei, e, is64);
            int d = load_idx_cs(ei, (long long)e + E, is64);
            if ((unsigned)s < (unsigned)n && (unsigned)d < (unsigned)n) {
                if (fast) {
                    // Branch-free: one red.v2 carries (pos, neg); inactive
                    // component adds +0.0f (exact).
                    float v  = __ldg(&g_val[s]);
                    float vp = fmaxf(v, 0.0f);
                    float vn = fmaxf(-v, 0.0f);
                    float* p = reinterpret_cast<float*>(&g_sb[d]);
                    asm volatile("red.global.add.v2.f32 [%0], {%1,%2};"
                                 :: "l"(p), "f"(vp), "f"(vn)
                                 : "memory");
                } else {
                    float4 m = __ldg(&g_h2d[s]);
                    float* p = reinterpret_cast<float*>(&out[d]);
                    asm volatile("red.global.add.v4.f32 [%0], {%1,%2,%3,%4};"
                                 :: "l"(p), "f"(m.x), "f"(m.y), "f"(m.z), "f"(m.w)
                                 : "memory");
                }
            }
        }
    }
    pdl_launch_dependents();
}

// ---------------- launch ----------------

template <typename F, typename... Args>
static void launch_pdl(F func, int grid, int block, Args... args) {
    cudaLaunchConfig_t cfg = {};
    cfg.gridDim  = dim3(grid, 1, 1);
    cfg.blockDim = dim3(block, 1, 1);
    cudaLaunchAttribute attr[1];
    attr[0].id = cudaLaunchAttributeProgrammaticStreamSerialization;
    attr[0].val.programmaticStreamSerializationAllowed = 1;
    cfg.attrs = attr;
    cfg.numAttrs = 1;
    cudaLaunchKernelEx(&cfg, func, args...);
}

extern "C" void kernel_launch(void* const* d_in, const int* in_sizes, int n_in,
                              void* d_out, int out_size) {
    const float* x  = (const float*)d_in[0];
    const void*  ei = d_in[1];                 // [2, E], int32 or int64
    const float* W1 = (const float*)d_in[2];
    const float* b1 = (const float*)d_in[3];
    const float* W2 = (const float*)d_in[4];
    const float* b2 = (const float*)d_in[5];
    float4* out = (float4*)d_out;

    int n = in_sizes[0];            // N nodes (C_in = 1)
    int E = in_sizes[1] / 2;        // element count is dtype-independent

    int nb_node = (n + TB - 1) / TB;
    int nb_edge = (E + TB * EPT - 1) / (TB * EPT);

    k_probe_init <<<nb_node, TB>>>(ei, E, n, b1);              // 1 (plain launch)
    launch_pdl(k_deg,      nb_edge, TB, ei, E, n);             // 2
    launch_pdl(k_dinv,     nb_node, TB, x, n);                 // 3
    launch_pdl(k_scatter1, nb_edge, TB, ei, E, n);             // 4
    launch_pdl(k_mid,      nb_node, TB, W1, b1, W2, out, n);   // 5
    launch_pdl(k_scatter2, nb_edge, TB, ei, out, E, n);        // 6
    launch_pdl(k_final,    nb_node, TB, W1, W2, b2, out, n);   // 7
}

// round 14
// speedup vs baseline: 1.0253x; 1.0004x over previous
#include <cuda_runtime.h>

#define NN 500000   // N_NODES upper bound
#define TB 256      // node-kernel block size
#define TBE 512     // edge-kernel block size (this round's knob)
#define EPT 4       // edges per thread in edge kernels

// Scratch (no cudaMalloc allowed).
__device__ int    g_is64;        // 1 if edge_index is int64, 0 if int32
__device__ int    g_b1zero;      // 1 if b1 == 0 (enables scalar layer-2 path)
__device__ float  g_deg [NN];    // degree (float; exact for counts < 2^24)
__device__ float  g_dinv[NN];    // deg^{-1/2}
__device__ float  g_v   [NN];    // dinv[i] * x[i]          (gather source, layer 1)
__device__ float  g_s   [NN];    // layer-1 accumulator (init = self-loop term)
__device__ float  g_val [NN];    // dinv[i]^2 * s[i] = dinv*pre  (gather, layer 2 fast path)
__device__ float  g_spos[NN];    // Σ max(val[s],0) at dst  (init = self-loop)
__device__ float  g_sneg[NN];    // Σ max(-val[s],0) at dst (init = self-loop)
__device__ float4 g_h2d [NN];    // dinv[i]*(relu(pre)@W2)  (gather, fallback path)

// ---------------- probe + degree init (fused) ----------------
__global__ void k_probe_init(const void* ei, int E, int n, const float* __restrict__ b1) {
    int i = blockIdx.x * blockDim.x + threadIdx.x;
    if (i < n) g_deg[i] = 1.0f;              // self-loop
    if (blockIdx.x == 0) {
        // dtype probe: as int64, genuine int64 indices are in [0,n).
        // int32 misread as int64 gives lo + hi*2^32, out of range unless hi==0.
        __shared__ int ok;
        if (threadIdx.x == 0) ok = 1;
        __syncthreads();
        const long long* p = (const long long*)ei;
        long long stride = E / blockDim.x;
        if (stride < 1) stride = 1;
        long long idx = (long long)threadIdx.x * stride;
        if (idx < E) {   // first E int64 slots in-bounds under BOTH interpretations
            long long v = p[idx];
            if (v < 0 || v >= (long long)n) ok = 0;
        }
        __syncthreads();
        if (threadIdx.x == 0) {
            g_is64 = ok;
            g_b1zero = (b1[0] == 0.0f && b1[1] == 0.0f &&
                        b1[2] == 0.0f && b1[3] == 0.0f) ? 1 : 0;
        }
    }
}

// ---------------- node kernels ----------------

__global__ void k_dinv(const float* __restrict__ x, int n) {
    int i = blockIdx.x * blockDim.x + threadIdx.x;
    if (i < n) {
        float di = rsqrtf(g_deg[i]);         // deg >= 1 always (self-loop)
        g_dinv[i] = di;
        float v = di * x[i];
        g_v[i] = v;
        g_s[i] = v;                          // self-loop contribution, layer 1
    }
}

__global__ void k_mid(const float* __restrict__ W1, const float* __restrict__ b1,
                      const float* __restrict__ W2,
                      float4* __restrict__ out, int n) {
    int i = blockIdx.x * blockDim.x + threadIdx.x;
    if (i >= n) return;
    float di  = g_dinv[i];
    float pre = di * g_s[i];
    float val = di * pre;
    g_val [i] = val;
    g_spos[i] = fmaxf(val, 0.0f);            // self-loop contribution, layer 2
    g_sneg[i] = fmaxf(-val, 0.0f);
    if (!g_b1zero) {                         // fallback representation (b1 != 0)
        float h[4];
#pragma unroll
        for (int c = 0; c < 4; c++)
            h[c] = fmaxf(fmaf(pre, __ldg(&W1[c]), __ldg(&b1[c])), 0.0f);
        float4 v;
        v.x = di * (h[0]*__ldg(&W2[0]) + h[1]*__ldg(&W2[4]) + h[2]*__ldg(&W2[8])  + h[3]*__ldg(&W2[12]));
        v.y = di * (h[0]*__ldg(&W2[1]) + h[1]*__ldg(&W2[5]) + h[2]*__ldg(&W2[9])  + h[3]*__ldg(&W2[13]));
        v.z = di * (h[0]*__ldg(&W2[2]) + h[1]*__ldg(&W2[6]) + h[2]*__ldg(&W2[10]) + h[3]*__ldg(&W2[14]));
        v.w = di * (h[0]*__ldg(&W2[3]) + h[1]*__ldg(&W2[7]) + h[2]*__ldg(&W2[11]) + h[3]*__ldg(&W2[15]));
        g_h2d[i] = v;
        out[i]   = v;
    }
}

__global__ void k_final(const float* __restrict__ W1, const float* __restrict__ W2,
                        const float* __restrict__ b2,
                        float4* __restrict__ out, int n) {
    int i = blockIdx.x * blockDim.x + threadIdx.x;
    if (i >= n) return;
    float di = g_dinv[i];
    if (g_b1zero) {
        float gp[4], gn[4];
#pragma unroll
        for (int k = 0; k < 4; k++) {
            float w = __ldg(&W1[k]);
            gp[k] = fmaxf(w, 0.0f);
            gn[k] = fmaxf(-w, 0.0f);
        }
        float sp = g_spos[i], sn = g_sneg[i];
        float o[4];
#pragma unroll
        for (int c = 0; c < 4; c++) {
            float up = gp[0]*__ldg(&W2[0*4+c]) + gp[1]*__ldg(&W2[1*4+c])
                     + gp[2]*__ldg(&W2[2*4+c]) + gp[3]*__ldg(&W2[3*4+c]);
            float un = gn[0]*__ldg(&W2[0*4+c]) + gn[1]*__ldg(&W2[1*4+c])
                     + gn[2]*__ldg(&W2[2*4+c]) + gn[3]*__ldg(&W2[3*4+c]);
            o[c] = fmaf(di, sp*up + sn*un, __ldg(&b2[c]));
        }
        out[i] = make_float4(o[0], o[1], o[2], o[3]);
    } else {
        float4 o = out[i];
        out[i] = make_float4(fmaf(di, o.x, __ldg(&b2[0])),
                             fmaf(di, o.y, __ldg(&b2[1])),
                             fmaf(di, o.z, __ldg(&b2[2])),
                             fmaf(di, o.w, __ldg(&b2[3])));
    }
}

// ---------------- edge kernels (R5 bodies; TBE block size) ----------------

__device__ __forceinline__ int load_idx_cs(const void* ei, long long e, int is64) {
    if (is64) return (int)__ldcs(((const long long*)ei) + e);
    return __ldcs(((const int*)ei) + e);
}

__global__ void __launch_bounds__(TBE) k_deg(const void* __restrict__ ei, int E, int n) {
    int is64 = g_is64;
    int e0 = blockIdx.x * blockDim.x * EPT + threadIdx.x;
    for (int k = 0; k < EPT; k++) {
        int e = e0 + k * blockDim.x;
        if (e < E) {
            int d = load_idx_cs(ei, (long long)e + E, is64);
            if ((unsigned)d < (unsigned)n) atomicAdd(&g_deg[d], 1.0f);
        }
    }
}

__global__ void __launch_bounds__(TBE) k_scatter1(const void* __restrict__ ei, int E, int n) {
    int is64 = g_is64;
    int e0 = blockIdx.x * blockDim.x * EPT + threadIdx.x;
    for (int k = 0; k < EPT; k++) {
        int e = e0 + k * blockDim.x;
        if (e < E) {
            int s = load_idx_cs(ei, e, is64);
            int d = load_idx_cs(ei, (long long)e + E, is64);
            if ((unsigned)s < (unsigned)n && (unsigned)d < (unsigned)n)
                atomicAdd(&g_s[d], __ldg(&g_v[s]));
        }
    }
}

__global__ void __launch_bounds__(TBE) k_scatter2(const void* __restrict__ ei,
                                                  float4* __restrict__ out, int E, int n) {
    int is64 = g_is64;
    int fast = g_b1zero;
    int e0 = blockIdx.x * blockDim.x * EPT + threadIdx.x;
    for (int k = 0; k < EPT; k++) {
        int e = e0 + k * blockDim.x;
        if (e < E) {
            int s = load_idx_cs(ei, e, is64);
            int d = load_idx_cs(ei, (long long)e + E, is64);
            if ((unsigned)s < (unsigned)n && (unsigned)d < (unsigned)n) {
                if (fast) {
                    float v = __ldg(&g_val[s]);
                    if (v >= 0.0f) atomicAdd(&g_spos[d], v);
                    else           atomicAdd(&g_sneg[d], -v);
                } else {
                    float4 m = __ldg(&g_h2d[s]);
                    float* p = reinterpret_cast<float*>(&out[d]);
                    asm volatile("red.global.add.v4.f32 [%0], {%1,%2,%3,%4};"
                                 :: "l"(p), "f"(m.x), "f"(m.y), "f"(m.z), "f"(m.w)
                                 : "memory");
                }
            }
        }
    }
}

// ---------------- launch ----------------

extern "C" void kernel_launch(void* const* d_in, const int* in_sizes, int n_in,
                              void* d_out, int out_size) {
    const float* x  = (const float*)d_in[0];
    const void*  ei = d_in[1];                 // [2, E], int32 or int64
    const float* W1 = (const float*)d_in[2];
    const float* b1 = (const float*)d_in[3];
    const float* W2 = (const float*)d_in[4];
    const float* b2 = (const float*)d_in[5];
    float4* out = (float4*)d_out;

    int n = in_sizes[0];            // N nodes (C_in = 1)
    int E = in_sizes[1] / 2;        // element count is dtype-independent

    int nb_node = (n + TB - 1) / TB;
    int nb_edge = (E + TBE * EPT - 1) / (TBE * EPT);

    k_probe_init <<<nb_node, TB>>>(ei, E, n, b1);        // 1
    k_deg        <<<nb_edge, TBE>>>(ei, E, n);           // 2
    k_dinv       <<<nb_node, TB>>>(x, n);                // 3
    k_scatter1   <<<nb_edge, TBE>>>(ei, E, n);           // 4
    k_mid        <<<nb_node, TB>>>(W1, b1, W2, out, n);  // 5
    k_scatter2   <<<nb_edge, TBE>>>(ei, out, E, n);      // 6
    k_final      <<<nb_node, TB>>>(W1, W2, b2, out, n);  // 7
}